// round 10
// baseline (speedup 1.0000x reference)
#include <cuda_runtime.h>
#include <cuda_fp16.h>
#include <cstdint>

// Problem constants
#define B_    4
#define CIN   128
#define COUT  128
#define H_    32
#define W_    128
#define L_    4096
#define NH    2
#define DK    64
#define BN_EPS 1e-5f

// q is pre-scaled by 0.125 * log2(e) so softmax is exp2(S)
#define QSCALE 0.18033688011112042f

// Device scratch (fp16 operands)
__device__ __half g_qhf[B_ * L_ * COUT];   // [b][l][c]  (pre-scaled)
__device__ __half g_khf[B_ * L_ * COUT];   // [b][l][c]
__device__ __half g_vhf[B_ * COUT * L_];   // [b][c][l]
__device__ float  g_att[B_ * COUT * L_];   // [b][c][l] fp32

#define SWZ128(off) ((off) ^ (((off) >> 3) & 0x70))
#define ONE2 0x3C003C00u   // fp16 {1.0, 1.0}

__device__ __forceinline__ uint32_t smem_u32(const void* p) {
    uint32_t a;
    asm("{ .reg .u64 t; cvta.to.shared.u64 t, %1; cvt.u32.u64 %0, t; }" : "=r"(a) : "l"(p));
    return a;
}
__device__ __forceinline__ void ldsm_x4(uint32_t* r, uint32_t addr) {
    asm volatile("ldmatrix.sync.aligned.m8n8.x4.shared.b16 {%0,%1,%2,%3}, [%4];"
                 : "=r"(r[0]), "=r"(r[1]), "=r"(r[2]), "=r"(r[3]) : "r"(addr));
}
__device__ __forceinline__ void mma_f16(float* d, const uint32_t* a, const uint32_t* b) {
    asm volatile(
        "mma.sync.aligned.m16n8k16.row.col.f32.f16.f16.f32 "
        "{%0,%1,%2,%3}, {%4,%5,%6,%7}, {%8,%9}, {%0,%1,%2,%3};"
        : "+f"(d[0]), "+f"(d[1]), "+f"(d[2]), "+f"(d[3])
        : "r"(a[0]), "r"(a[1]), "r"(a[2]), "r"(a[3]), "r"(b[0]), "r"(b[1]));
}
__device__ __forceinline__ void cp16(uint32_t dst, const void* src) {
    asm volatile("cp.async.ca.shared.global [%0], [%1], 16;" :: "r"(dst), "l"(src));
}
__device__ __forceinline__ uint32_t exp2_f16x2(float lo, float hi) {
    uint32_t s, p;
    asm("cvt.rn.f16x2.f32 %0, %1, %2;" : "=r"(s) : "f"(hi), "f"(lo));
    asm("ex2.approx.f16x2 %0, %1;" : "=r"(p) : "r"(s));
    return p;
}

// ---------------------------------------------------------------------------
// Kernel 1: QKV projection via HMMA, batched-MLP loads, fp16 outputs.
// ---------------------------------------------------------------------------
#define QKV_SMEM 65536
__global__ __launch_bounds__(256, 2)
void qkv_hmma(const float* __restrict__ x,
              const float* __restrict__ wq, const float* __restrict__ bq,
              const float* __restrict__ wk, const float* __restrict__ bk,
              const float* __restrict__ wv, const float* __restrict__ bv)
{
    extern __shared__ char smc[];
    const uint32_t smb = smem_u32(smc);
    const int tid = threadIdx.x, wid = tid >> 5, lane = tid & 31;
    const int lt = blockIdx.x * 128, b = blockIdx.y, which = blockIdx.z;
    const int g = lane >> 2, tig = lane & 3;

    const float* w    = (which == 0) ? wq : (which == 1) ? wk : wv;
    const float* bias = (which == 0) ? bq : (which == 1) ? bk : bv;

    float4 xv[16];
#pragma unroll
    for (int u = 0; u < 16; u++) {
        int it = tid + u * 256;
        int l = it & 127, i4 = (it >> 7) * 4;
        const float* xp = &x[(size_t)(b * CIN + i4) * L_ + lt + l];
        xv[u].x = xp[0];
        xv[u].y = xp[L_];
        xv[u].z = xp[2 * L_];
        xv[u].w = xp[3 * L_];
    }
#pragma unroll
    for (int u = 0; u < 16; u++) {
        int it = tid + u * 256;
        int l = it & 127, i4 = (it >> 7) * 4;
        __half r[4] = {__float2half(xv[u].x), __float2half(xv[u].y),
                       __float2half(xv[u].z), __float2half(xv[u].w)};
        char* base = smc + ((i4 >> 6) ? 16384 : 0);
        *(uint2*)(base + SWZ128(l * 128 + (i4 & 63) * 2)) = *(uint2*)r;
    }
    float4 wv4[16];
#pragma unroll
    for (int u = 0; u < 16; u++) {
        int it = tid + u * 256;
        int o = it >> 5, i4 = (it & 31) * 4;
        wv4[u] = *(const float4*)&w[o * 128 + i4];
    }
#pragma unroll
    for (int u = 0; u < 16; u++) {
        int it = tid + u * 256;
        int o = it >> 5, i4 = (it & 31) * 4;
        __half r[4] = {__float2half(wv4[u].x), __float2half(wv4[u].y),
                       __float2half(wv4[u].z), __float2half(wv4[u].w)};
        char* base = smc + 32768 + ((i4 >> 6) ? 16384 : 0);
        *(uint2*)(base + SWZ128(o * 128 + (i4 & 63) * 2)) = *(uint2*)r;
    }
    __syncthreads();

    const uint32_t arow = wid * 16 + (lane & 7) + ((lane >> 3) & 1) * 8;
    const uint32_t acol = (lane >> 4) * 16;
    const uint32_t brow_lo  = (lane & 7) + ((lane >> 4) << 3);
    const uint32_t bcol_sel = ((lane >> 3) & 1) * 16;
    const int c0 = wid * 16 + g;

    float acc[16][4];
#pragma unroll
    for (int i = 0; i < 16; i++)
#pragma unroll
        for (int j = 0; j < 4; j++) acc[i][j] = 0.f;

#pragma unroll
    for (int kc = 0; kc < 8; kc++) {
        const uint32_t hoff = ((kc >> 2) ? 16384 : 0);
        const int ks = kc & 3;
        uint32_t a4[4];
        ldsm_x4(a4, smb + 32768 + hoff + SWZ128(arow * 128 + ks * 32 + acol));
#pragma unroll
        for (int np = 0; np < 8; np++) {
            uint32_t b4[4];
            ldsm_x4(b4, smb + hoff + SWZ128((np * 16 + brow_lo) * 128 + ks * 32 + bcol_sel));
            mma_f16(acc[2 * np],     a4, b4);
            mma_f16(acc[2 * np + 1], a4, b4 + 2);
        }
    }

    const float b0 = bias[c0], b1 = bias[c0 + 8];
    const float s = (which == 0) ? QSCALE : 1.0f;
    __syncthreads();

    if (which < 2) {
        __half* st = (__half*)smc;
#pragma unroll
        for (int nt = 0; nt < 16; nt++) {
            const int l0 = nt * 8 + tig * 2;
            st[l0 * 128 + c0]           = __float2half((acc[nt][0] + b0) * s);
            st[(l0 + 1) * 128 + c0]     = __float2half((acc[nt][1] + b0) * s);
            st[l0 * 128 + c0 + 8]       = __float2half((acc[nt][2] + b1) * s);
            st[(l0 + 1) * 128 + c0 + 8] = __float2half((acc[nt][3] + b1) * s);
        }
        __syncthreads();
        __half* dst = (which == 0) ? g_qhf : g_khf;
        uint4* dg = (uint4*)&dst[(size_t)(b * L_ + lt) * 128];
        const uint4* sg = (const uint4*)smc;
        for (int i = tid; i < 2048; i += 256) dg[i] = sg[i];
    } else {
        uint32_t* st = (uint32_t*)smc;
#pragma unroll
        for (int nt = 0; nt < 16; nt++) {
            const int lp = (nt * 8 + tig * 2) >> 1;
            __half2 v0 = __floats2half2_rn(acc[nt][0] + b0, acc[nt][1] + b0);
            __half2 v1 = __floats2half2_rn(acc[nt][2] + b1, acc[nt][3] + b1);
            st[c0 * 64 + lp]       = *(uint32_t*)&v0;
            st[(c0 + 8) * 64 + lp] = *(uint32_t*)&v1;
        }
        __syncthreads();
        for (int i = tid; i < 2048; i += 256) {
            int c = i >> 4, seg = i & 15;
            *(uint4*)&g_vhf[(size_t)(b * COUT + c) * L_ + lt + seg * 8] =
                ((const uint4*)smc)[i];
        }
    }
}

// ---------------------------------------------------------------------------
// Kernel 2: FMHA. CTA = (128-q tile, head, batch), 8 warps; warp owns
// 16 q-rows x ALL 128 keys (no split-K, no merge). Streaming S-phase:
// per 16-key block compute S (8 regs), exp2 immediately -> packed pf A-frags.
// Low regs (~116) => 2 CTAs/SM, 256 CTAs = single wave.
// ---------------------------------------------------------------------------
#define OFF_Q   0
#define OFF_K   16384
#define OFF_V   49152
#define SMEM_ATTN 81920

__device__ __forceinline__ void load_kv_tile(uint32_t smb, int tid, int b, int head,
                                             int kt, int s)
{
    const char* kb = (const char*)g_khf;
    const uint32_t kdst = smb + OFF_K + s * 16384;
    for (int i = tid; i < 1024; i += 256) {
        int r = i >> 3, ch = i & 7;
        const char* src = kb + ((size_t)(b * L_ + kt + r) * COUT + head * DK) * 2 + ch * 16;
        cp16(kdst + SWZ128(r * 128 + ch * 16), src);
    }
    const char* vb = (const char*)g_vhf;
    const uint32_t vdst = smb + OFF_V + s * 16384;
    for (int i = tid; i < 1024; i += 256) {
        int half = i >> 9, rem = i & 511;
        int d = rem >> 3, ch = rem & 7;
        const char* src = vb + ((size_t)(b * COUT + head * DK + d) * L_ + kt + half * 64 + ch * 8) * 2;
        cp16(vdst + half * 8192 + SWZ128(d * 128 + ch * 16), src);
    }
}

__global__ __launch_bounds__(256, 2)
void attn_mma_kernel()
{
    extern __shared__ char smc[];
    const uint32_t smb = smem_u32(smc);

    const int tid  = threadIdx.x;
    const int wid  = tid >> 5;
    const int lane = tid & 31;
    const int qt   = blockIdx.x * 128;
    const int head = blockIdx.y;
    const int b    = blockIdx.z;

    const int g   = lane >> 2;
    const int tig = lane & 3;

    {
        const char* qb = (const char*)g_qhf;
        for (int i = tid; i < 1024; i += 256) {
            int r = i >> 3, ch = i & 7;
            const char* src = qb + ((size_t)(b * L_ + qt + r) * COUT + head * DK) * 2 + ch * 16;
            cp16(smb + OFF_Q + SWZ128(r * 128 + ch * 16), src);
        }
        load_kv_tile(smb, tid, b, head, 0, 0);
        asm volatile("cp.async.commit_group;" ::: "memory");
    }

    uint32_t qhr[4][4];        // Q frags for this warp's 16 rows
    float O[8][4];             // 16q x 64d accumulators
    float Osum[4];             // ones-MMA rowsum
#pragma unroll
    for (int i = 0; i < 8; i++)
#pragma unroll
        for (int j = 0; j < 4; j++) O[i][j] = 0.f;
#pragma unroll
    for (int j = 0; j < 4; j++) Osum[j] = 0.f;
    const uint32_t ones[2] = {ONE2, ONE2};

    const uint32_t brow_lo  = (lane & 7) + ((lane >> 4) << 3);
    const uint32_t bcol_sel = ((lane >> 3) & 1) * 16;

    for (int t = 0; t < 32; t++) {
        __syncthreads();
        if (t + 1 < 32) {
            load_kv_tile(smb, tid, b, head, (t + 1) * 128, (t + 1) & 1);
            asm volatile("cp.async.commit_group;" ::: "memory");
            asm volatile("cp.async.wait_group 1;" ::: "memory");
        } else {
            asm volatile("cp.async.wait_group 0;" ::: "memory");
        }
        __syncthreads();

        if (t == 0) {
            const uint32_t arow = wid * 16 + (lane & 7) + ((lane >> 3) & 1) * 8;
#pragma unroll
            for (int ks = 0; ks < 4; ks++) {
                uint32_t colb = ks * 32 + (lane >> 4) * 16;
                ldsm_x4(qhr[ks], smb + OFF_Q + SWZ128(arow * 128 + colb));
            }
        }

        const uint32_t kbase = smb + OFF_K + (t & 1) * 16384;
        const uint32_t vbase = smb + OFF_V + (t & 1) * 16384;

        // ---- streaming S + exp: per 16-key block ----
        uint32_t pf[8][4];    // P A-frags, 128 keys
#pragma unroll
        for (int nb = 0; nb < 8; nb++) {
            float S8[2][4];
#pragma unroll
            for (int i = 0; i < 2; i++)
#pragma unroll
                for (int j = 0; j < 4; j++) S8[i][j] = 0.f;
            uint32_t row = nb * 16 + brow_lo;
#pragma unroll
            for (int ks = 0; ks < 4; ks++) {
                uint32_t bh[4];
                ldsm_x4(bh, kbase + SWZ128(row * 128 + ks * 32 + bcol_sel));
                mma_f16(S8[0], qhr[ks], bh);
                mma_f16(S8[1], qhr[ks], bh + 2);
            }
            pf[nb][0] = exp2_f16x2(S8[0][0], S8[0][1]);
            pf[nb][1] = exp2_f16x2(S8[0][2], S8[0][3]);
            pf[nb][2] = exp2_f16x2(S8[1][0], S8[1][1]);
            pf[nb][3] = exp2_f16x2(S8[1][2], S8[1][3]);
            mma_f16(Osum, pf[nb], ones);
        }

        // ---- O += P·V^T ----
#pragma unroll
        for (int kk = 0; kk < 8; kk++) {
            const uint32_t vb2 = vbase + ((kk >= 4) ? 8192 : 0);
#pragma unroll
            for (int dp = 0; dp < 4; dp++) {
                uint32_t vfr[4];
                uint32_t row = dp * 16 + brow_lo;
                ldsm_x4(vfr, vb2 + SWZ128(row * 128 + (kk & 3) * 32 + bcol_sel));
                mma_f16(O[2 * dp],     pf[kk], vfr);
                mma_f16(O[2 * dp + 1], pf[kk], vfr + 2);
            }
        }
    }

    // Osum[0] = rowsum(q row g), Osum[2] = rowsum(q row g+8) — exact, all lanes
    const float inv0 = 1.f / Osum[0];
    const float inv1 = 1.f / Osum[2];

    __syncthreads();
    float* Ost = (float*)smc;   // [64 d][132] fp32 = 33792 B
    const int q0 = wid * 16 + g;
#pragma unroll
    for (int dt = 0; dt < 8; dt++) {
        int d = dt * 8 + 2 * tig;
        Ost[(d)     * 132 + q0]     = O[dt][0] * inv0;
        Ost[(d + 1) * 132 + q0]     = O[dt][1] * inv0;
        Ost[(d)     * 132 + q0 + 8] = O[dt][2] * inv1;
        Ost[(d + 1) * 132 + q0 + 8] = O[dt][3] * inv1;
    }
    __syncthreads();

    float* og = g_att + (size_t)(b * COUT + head * DK) * L_ + qt;
    for (int i = tid; i < 64 * 128; i += 256) {
        int d = i >> 7, l = i & 127;
        og[(size_t)d * L_ + l] = Ost[d * 132 + l];
    }
}

// ---------------------------------------------------------------------------
// Kernel 3: fc_out + BN + PReLU via fp16 hi/lo HMMA (unchanged).
// ---------------------------------------------------------------------------
#define FC_SMEM 131072
__global__ __launch_bounds__(256, 1)
void fc_hmma(const float* __restrict__ fcw, const float* __restrict__ fcb,
             const float* __restrict__ gamma, const float* __restrict__ beta,
             const float* __restrict__ mean,  const float* __restrict__ var,
             const float* __restrict__ prelu, float* __restrict__ y)
{
    extern __shared__ char smc[];
    const uint32_t smb = smem_u32(smc);
    const int tid = threadIdx.x, wid = tid >> 5, lane = tid & 31;
    const int rt = blockIdx.x * 128;
    const int g = lane >> 2, tig = lane & 3;

    for (int it = tid; it < 4096; it += 256) {
        int r = it >> 5, w4 = (it & 31) * 4;
        float4 v = *(const float4*)&g_att[(size_t)(rt + r) * 128 + w4];
        __half hi[4], lo[4];
        hi[0] = __float2half(v.x); lo[0] = __float2half(v.x - __half2float(hi[0]));
        hi[1] = __float2half(v.y); lo[1] = __float2half(v.y - __half2float(hi[1]));
        hi[2] = __float2half(v.z); lo[2] = __float2half(v.z - __half2float(hi[2]));
        hi[3] = __float2half(v.w); lo[3] = __float2half(v.w - __half2float(hi[3]));
        uint32_t off = SWZ128(r * 128 + (w4 & 63) * 2) + ((w4 >> 6) ? 16384 : 0);
        *(uint2*)(smc + off)         = *(uint2*)hi;
        *(uint2*)(smc + 32768 + off) = *(uint2*)lo;
    }
    for (int it = tid; it < 4096; it += 256) {
        int o = it >> 5, w4 = (it & 31) * 4;
        float4 v = *(const float4*)&fcw[o * 128 + w4];
        __half hi[4], lo[4];
        hi[0] = __float2half(v.x); lo[0] = __float2half(v.x - __half2float(hi[0]));
        hi[1] = __float2half(v.y); lo[1] = __float2half(v.y - __half2float(hi[1]));
        hi[2] = __float2half(v.z); lo[2] = __float2half(v.z - __half2float(hi[2]));
        hi[3] = __float2half(v.w); lo[3] = __float2half(v.w - __half2float(hi[3]));
        uint32_t off = SWZ128(o * 128 + (w4 & 63) * 2) + ((w4 >> 6) ? 16384 : 0);
        *(uint2*)(smc + 65536 + off) = *(uint2*)hi;
        *(uint2*)(smc + 98304 + off) = *(uint2*)lo;
    }
    __syncthreads();

    const uint32_t arow = wid * 16 + (lane & 7) + ((lane >> 3) & 1) * 8;
    const uint32_t acol = (lane >> 4) * 16;
    const uint32_t brow_lo  = (lane & 7) + ((lane >> 4) << 3);
    const uint32_t bcol_sel = ((lane >> 3) & 1) * 16;

    float acc[16][4];
#pragma unroll
    for (int i = 0; i < 16; i++)
#pragma unroll
        for (int j = 0; j < 4; j++) acc[i][j] = 0.f;

#pragma unroll
    for (int kc = 0; kc < 8; kc++) {
        const uint32_t hoff = ((kc >> 2) ? 16384 : 0);
        const int ks = kc & 3;
        uint32_t ah[4], al[4];
        uint32_t aoff = SWZ128(arow * 128 + ks * 32 + acol) + hoff;
        ldsm_x4(ah, smb + aoff);
        ldsm_x4(al, smb + 32768 + aoff);

        uint32_t bh[8][4], bl[8][4];
#pragma unroll
        for (int np = 0; np < 8; np++) {
            uint32_t boff = SWZ128((np * 16 + brow_lo) * 128 + ks * 32 + bcol_sel) + hoff;
            ldsm_x4(bh[np], smb + 65536 + boff);
            ldsm_x4(bl[np], smb + 98304 + boff);
        }
#pragma unroll
        for (int np = 0; np < 8; np++) {
            mma_f16(acc[2 * np],     ah, bh[np]);
            mma_f16(acc[2 * np + 1], ah, bh[np] + 2);
        }
#pragma unroll
        for (int np = 0; np < 8; np++) {
            mma_f16(acc[2 * np],     ah, bl[np]);
            mma_f16(acc[2 * np + 1], ah, bl[np] + 2);
        }
#pragma unroll
        for (int np = 0; np < 8; np++) {
            mma_f16(acc[2 * np],     al, bh[np]);
            mma_f16(acc[2 * np + 1], al, bh[np] + 2);
        }
    }

    const float slope = prelu[0];
    const int r0 = rt + wid * 16 + g;
#pragma unroll
    for (int half = 0; half < 2; half++) {
        const int r = r0 + 8 * half;
        const int c = (r >> 5) & 127;
        const float sc = rsqrtf(var[c] + BN_EPS) * gamma[c];
        const float sh = beta[c] - mean[c] * sc;
#pragma unroll
        for (int nt = 0; nt < 16; nt++) {
            const int o = nt * 8 + tig * 2;
            float v0 = (acc[nt][2 * half]     + fcb[o])     * sc + sh;
            float v1 = (acc[nt][2 * half + 1] + fcb[o + 1]) * sc + sh;
            v0 = (v0 > 0.f) ? v0 : slope * v0;
            v1 = (v1 > 0.f) ? v1 : slope * v1;
            *(float2*)&y[(size_t)r * 128 + o] = make_float2(v0, v1);
        }
    }
}

// ---------------------------------------------------------------------------
extern "C" void kernel_launch(void* const* d_in, const int* in_sizes, int n_in,
                              void* d_out, int out_size)
{
    const float* x     = (const float*)d_in[0];
    const float* wq    = (const float*)d_in[1];
    const float* bq    = (const float*)d_in[2];
    const float* wk    = (const float*)d_in[3];
    const float* bk    = (const float*)d_in[4];
    const float* wv    = (const float*)d_in[5];
    const float* bv    = (const float*)d_in[6];
    const float* fc_w  = (const float*)d_in[7];
    const float* fc_b  = (const float*)d_in[8];
    const float* gam   = (const float*)d_in[9];
    const float* bet   = (const float*)d_in[10];
    const float* mean  = (const float*)d_in[11];
    const float* var   = (const float*)d_in[12];
    const float* prelu = (const float*)d_in[13];
    float* y = (float*)d_out;

    cudaFuncSetAttribute(qkv_hmma, cudaFuncAttributeMaxDynamicSharedMemorySize, QKV_SMEM);
    cudaFuncSetAttribute(attn_mma_kernel, cudaFuncAttributeMaxDynamicSharedMemorySize, SMEM_ATTN);
    cudaFuncSetAttribute(fc_hmma, cudaFuncAttributeMaxDynamicSharedMemorySize, FC_SMEM);

    qkv_hmma<<<dim3(32, B_, 3), 256, QKV_SMEM>>>(x, wq, bq, wk, bk, wv, bv);
    attn_mma_kernel<<<dim3(L_ / 128, NH, B_), 256, SMEM_ATTN>>>();
    fc_hmma<<<128, 256, FC_SMEM>>>(fc_w, fc_b, gam, bet, mean, var, prelu, y);
}

// round 11
// speedup vs baseline: 1.1597x; 1.1597x over previous
#include <cuda_runtime.h>
#include <cuda_fp16.h>
#include <cstdint>

// Problem constants
#define B_    4
#define CIN   128
#define COUT  128
#define H_    32
#define W_    128
#define L_    4096
#define NH    2
#define DK    64
#define BN_EPS 1e-5f

// q is pre-scaled by 0.125 * log2(e) so softmax is exp2(S)
#define QSCALE 0.18033688011112042f

// Device scratch (fp16 operands)
__device__ __half g_qhf[B_ * L_ * COUT];   // [b][l][c]  (pre-scaled)
__device__ __half g_khf[B_ * L_ * COUT];   // [b][l][c]
__device__ __half g_vhf[B_ * COUT * L_];   // [b][c][l]
__device__ float  g_att[B_ * COUT * L_];   // [b][c][l] fp32

#define SWZ128(off) ((off) ^ (((off) >> 3) & 0x70))
#define ONE2 0x3C003C00u   // fp16 {1.0, 1.0}

__device__ __forceinline__ uint32_t smem_u32(const void* p) {
    uint32_t a;
    asm("{ .reg .u64 t; cvta.to.shared.u64 t, %1; cvt.u32.u64 %0, t; }" : "=r"(a) : "l"(p));
    return a;
}
__device__ __forceinline__ void ldsm_x4(uint32_t* r, uint32_t addr) {
    asm volatile("ldmatrix.sync.aligned.m8n8.x4.shared.b16 {%0,%1,%2,%3}, [%4];"
                 : "=r"(r[0]), "=r"(r[1]), "=r"(r[2]), "=r"(r[3]) : "r"(addr));
}
__device__ __forceinline__ void mma_f16(float* d, const uint32_t* a, const uint32_t* b) {
    asm volatile(
        "mma.sync.aligned.m16n8k16.row.col.f32.f16.f16.f32 "
        "{%0,%1,%2,%3}, {%4,%5,%6,%7}, {%8,%9}, {%0,%1,%2,%3};"
        : "+f"(d[0]), "+f"(d[1]), "+f"(d[2]), "+f"(d[3])
        : "r"(a[0]), "r"(a[1]), "r"(a[2]), "r"(a[3]), "r"(b[0]), "r"(b[1]));
}
__device__ __forceinline__ void cp16(uint32_t dst, const void* src) {
    asm volatile("cp.async.ca.shared.global [%0], [%1], 16;" :: "r"(dst), "l"(src));
}
__device__ __forceinline__ uint32_t exp2_f16x2(float lo, float hi) {
    uint32_t s, p;
    asm("cvt.rn.f16x2.f32 %0, %1, %2;" : "=r"(s) : "f"(hi), "f"(lo));
    asm("ex2.approx.f16x2 %0, %1;" : "=r"(p) : "r"(s));
    return p;
}

// ---------------------------------------------------------------------------
// Kernel 1: QKV projection via HMMA, batched-MLP loads, fp16 outputs.
// ---------------------------------------------------------------------------
#define QKV_SMEM 65536
__global__ __launch_bounds__(256, 2)
void qkv_hmma(const float* __restrict__ x,
              const float* __restrict__ wq, const float* __restrict__ bq,
              const float* __restrict__ wk, const float* __restrict__ bk,
              const float* __restrict__ wv, const float* __restrict__ bv)
{
    extern __shared__ char smc[];
    const uint32_t smb = smem_u32(smc);
    const int tid = threadIdx.x, wid = tid >> 5, lane = tid & 31;
    const int lt = blockIdx.x * 128, b = blockIdx.y, which = blockIdx.z;
    const int g = lane >> 2, tig = lane & 3;

    const float* w    = (which == 0) ? wq : (which == 1) ? wk : wv;
    const float* bias = (which == 0) ? bq : (which == 1) ? bk : bv;

    float4 xv[16];
#pragma unroll
    for (int u = 0; u < 16; u++) {
        int it = tid + u * 256;
        int l = it & 127, i4 = (it >> 7) * 4;
        const float* xp = &x[(size_t)(b * CIN + i4) * L_ + lt + l];
        xv[u].x = xp[0];
        xv[u].y = xp[L_];
        xv[u].z = xp[2 * L_];
        xv[u].w = xp[3 * L_];
    }
#pragma unroll
    for (int u = 0; u < 16; u++) {
        int it = tid + u * 256;
        int l = it & 127, i4 = (it >> 7) * 4;
        __half r[4] = {__float2half(xv[u].x), __float2half(xv[u].y),
                       __float2half(xv[u].z), __float2half(xv[u].w)};
        char* base = smc + ((i4 >> 6) ? 16384 : 0);
        *(uint2*)(base + SWZ128(l * 128 + (i4 & 63) * 2)) = *(uint2*)r;
    }
    float4 wv4[16];
#pragma unroll
    for (int u = 0; u < 16; u++) {
        int it = tid + u * 256;
        int o = it >> 5, i4 = (it & 31) * 4;
        wv4[u] = *(const float4*)&w[o * 128 + i4];
    }
#pragma unroll
    for (int u = 0; u < 16; u++) {
        int it = tid + u * 256;
        int o = it >> 5, i4 = (it & 31) * 4;
        __half r[4] = {__float2half(wv4[u].x), __float2half(wv4[u].y),
                       __float2half(wv4[u].z), __float2half(wv4[u].w)};
        char* base = smc + 32768 + ((i4 >> 6) ? 16384 : 0);
        *(uint2*)(base + SWZ128(o * 128 + (i4 & 63) * 2)) = *(uint2*)r;
    }
    __syncthreads();

    const uint32_t arow = wid * 16 + (lane & 7) + ((lane >> 3) & 1) * 8;
    const uint32_t acol = (lane >> 4) * 16;
    const uint32_t brow_lo  = (lane & 7) + ((lane >> 4) << 3);
    const uint32_t bcol_sel = ((lane >> 3) & 1) * 16;
    const int c0 = wid * 16 + g;

    float acc[16][4];
#pragma unroll
    for (int i = 0; i < 16; i++)
#pragma unroll
        for (int j = 0; j < 4; j++) acc[i][j] = 0.f;

#pragma unroll
    for (int kc = 0; kc < 8; kc++) {
        const uint32_t hoff = ((kc >> 2) ? 16384 : 0);
        const int ks = kc & 3;
        uint32_t a4[4];
        ldsm_x4(a4, smb + 32768 + hoff + SWZ128(arow * 128 + ks * 32 + acol));
#pragma unroll
        for (int np = 0; np < 8; np++) {
            uint32_t b4[4];
            ldsm_x4(b4, smb + hoff + SWZ128((np * 16 + brow_lo) * 128 + ks * 32 + bcol_sel));
            mma_f16(acc[2 * np],     a4, b4);
            mma_f16(acc[2 * np + 1], a4, b4 + 2);
        }
    }

    const float b0 = bias[c0], b1 = bias[c0 + 8];
    const float s = (which == 0) ? QSCALE : 1.0f;
    __syncthreads();

    if (which < 2) {
        __half* st = (__half*)smc;
#pragma unroll
        for (int nt = 0; nt < 16; nt++) {
            const int l0 = nt * 8 + tig * 2;
            st[l0 * 128 + c0]           = __float2half((acc[nt][0] + b0) * s);
            st[(l0 + 1) * 128 + c0]     = __float2half((acc[nt][1] + b0) * s);
            st[l0 * 128 + c0 + 8]       = __float2half((acc[nt][2] + b1) * s);
            st[(l0 + 1) * 128 + c0 + 8] = __float2half((acc[nt][3] + b1) * s);
        }
        __syncthreads();
        __half* dst = (which == 0) ? g_qhf : g_khf;
        uint4* dg = (uint4*)&dst[(size_t)(b * L_ + lt) * 128];
        const uint4* sg = (const uint4*)smc;
        for (int i = tid; i < 2048; i += 256) dg[i] = sg[i];
    } else {
        uint32_t* st = (uint32_t*)smc;
#pragma unroll
        for (int nt = 0; nt < 16; nt++) {
            const int lp = (nt * 8 + tig * 2) >> 1;
            __half2 v0 = __floats2half2_rn(acc[nt][0] + b0, acc[nt][1] + b0);
            __half2 v1 = __floats2half2_rn(acc[nt][2] + b1, acc[nt][3] + b1);
            st[c0 * 64 + lp]       = *(uint32_t*)&v0;
            st[(c0 + 8) * 64 + lp] = *(uint32_t*)&v1;
        }
        __syncthreads();
        for (int i = tid; i < 2048; i += 256) {
            int c = i >> 4, seg = i & 15;
            *(uint4*)&g_vhf[(size_t)(b * COUT + c) * L_ + lt + seg * 8] =
                ((const uint4*)smc)[i];
        }
    }
}

// ---------------------------------------------------------------------------
// Kernel 2: FMHA. CTA = (128-q tile, head, batch), 4 WARPS (128 thr);
// warp owns 32 q-rows (2 m-tiles) x all 128 keys. Fused per-16-key block:
// S MMA -> exp2 -> rowsum MMA -> PV MMA. K/V frags shared across m-tiles
// (crossbar halved vs R10); 2-way m-tile ILP; 2 CTAs/SM.
// ---------------------------------------------------------------------------
#define OFF_Q   0
#define OFF_K   16384
#define OFF_V   49152
#define SMEM_ATTN 81920

__device__ __forceinline__ void load_kv_tile(uint32_t smb, int tid, int b, int head,
                                             int kt, int s)
{
    const char* kb = (const char*)g_khf;
    const uint32_t kdst = smb + OFF_K + s * 16384;
    for (int i = tid; i < 1024; i += 128) {
        int r = i >> 3, ch = i & 7;
        const char* src = kb + ((size_t)(b * L_ + kt + r) * COUT + head * DK) * 2 + ch * 16;
        cp16(kdst + SWZ128(r * 128 + ch * 16), src);
    }
    const char* vb = (const char*)g_vhf;
    const uint32_t vdst = smb + OFF_V + s * 16384;
    for (int i = tid; i < 1024; i += 128) {
        int half = i >> 9, rem = i & 511;
        int d = rem >> 3, ch = rem & 7;
        const char* src = vb + ((size_t)(b * COUT + head * DK + d) * L_ + kt + half * 64 + ch * 8) * 2;
        cp16(vdst + half * 8192 + SWZ128(d * 128 + ch * 16), src);
    }
}

__global__ __launch_bounds__(128, 2)
void attn_mma_kernel()
{
    extern __shared__ char smc[];
    const uint32_t smb = smem_u32(smc);

    const int tid  = threadIdx.x;
    const int wid  = tid >> 5;
    const int lane = tid & 31;
    const int qt   = blockIdx.x * 128;
    const int head = blockIdx.y;
    const int b    = blockIdx.z;

    const int g   = lane >> 2;
    const int tig = lane & 3;

    {
        const char* qb = (const char*)g_qhf;
        for (int i = tid; i < 1024; i += 128) {
            int r = i >> 3, ch = i & 7;
            const char* src = qb + ((size_t)(b * L_ + qt + r) * COUT + head * DK) * 2 + ch * 16;
            cp16(smb + OFF_Q + SWZ128(r * 128 + ch * 16), src);
        }
        load_kv_tile(smb, tid, b, head, 0, 0);
        asm volatile("cp.async.commit_group;" ::: "memory");
    }

    uint32_t qhr[2][4][4];     // [mi][ks][4] Q frags: rows wid*32 + mi*16 ..
    float O[2][8][4];          // [mi][dt][4] accumulators (32q x 64d)
    float Osum[2][4];          // [mi] ones-MMA rowsums
#pragma unroll
    for (int mi = 0; mi < 2; mi++) {
#pragma unroll
        for (int i = 0; i < 8; i++)
#pragma unroll
            for (int j = 0; j < 4; j++) O[mi][i][j] = 0.f;
#pragma unroll
        for (int j = 0; j < 4; j++) Osum[mi][j] = 0.f;
    }
    const uint32_t ones[2] = {ONE2, ONE2};

    const uint32_t brow_lo  = (lane & 7) + ((lane >> 4) << 3);
    const uint32_t bcol_sel = ((lane >> 3) & 1) * 16;

    for (int t = 0; t < 32; t++) {
        __syncthreads();
        if (t + 1 < 32) {
            load_kv_tile(smb, tid, b, head, (t + 1) * 128, (t + 1) & 1);
            asm volatile("cp.async.commit_group;" ::: "memory");
            asm volatile("cp.async.wait_group 1;" ::: "memory");
        } else {
            asm volatile("cp.async.wait_group 0;" ::: "memory");
        }
        __syncthreads();

        if (t == 0) {
#pragma unroll
            for (int mi = 0; mi < 2; mi++) {
                const uint32_t arow = wid * 32 + mi * 16 + (lane & 7) + ((lane >> 3) & 1) * 8;
#pragma unroll
                for (int ks = 0; ks < 4; ks++) {
                    uint32_t colb = ks * 32 + (lane >> 4) * 16;
                    ldsm_x4(qhr[mi][ks], smb + OFF_Q + SWZ128(arow * 128 + colb));
                }
            }
        }

        const uint32_t kbase = smb + OFF_K + (t & 1) * 16384;
        const uint32_t vbase = smb + OFF_V + (t & 1) * 16384;

        // ---- fused per 16-key block: S -> exp2 -> rowsum + PV ----
#pragma unroll
        for (int nb = 0; nb < 8; nb++) {
            float S8[2][2][4];   // [mi][n-half][4]
#pragma unroll
            for (int mi = 0; mi < 2; mi++)
#pragma unroll
                for (int i = 0; i < 2; i++)
#pragma unroll
                    for (int j = 0; j < 4; j++) S8[mi][i][j] = 0.f;

            const uint32_t krow = nb * 16 + brow_lo;
#pragma unroll
            for (int ks = 0; ks < 4; ks++) {
                uint32_t bh[4];
                ldsm_x4(bh, kbase + SWZ128(krow * 128 + ks * 32 + bcol_sel));
                mma_f16(S8[0][0], qhr[0][ks], bh);
                mma_f16(S8[0][1], qhr[0][ks], bh + 2);
                mma_f16(S8[1][0], qhr[1][ks], bh);
                mma_f16(S8[1][1], qhr[1][ks], bh + 2);
            }

            uint32_t pf[2][4];
#pragma unroll
            for (int mi = 0; mi < 2; mi++) {
                pf[mi][0] = exp2_f16x2(S8[mi][0][0], S8[mi][0][1]);
                pf[mi][1] = exp2_f16x2(S8[mi][0][2], S8[mi][0][3]);
                pf[mi][2] = exp2_f16x2(S8[mi][1][0], S8[mi][1][1]);
                pf[mi][3] = exp2_f16x2(S8[mi][1][2], S8[mi][1][3]);
                mma_f16(Osum[mi], pf[mi], ones);
            }

            // PV over this 16-key slice (V cols nb*16..+16)
            const uint32_t vb2 = vbase + ((nb >= 4) ? 8192 : 0);
#pragma unroll
            for (int dp = 0; dp < 4; dp++) {
                uint32_t vfr[4];
                uint32_t row = dp * 16 + brow_lo;
                ldsm_x4(vfr, vb2 + SWZ128(row * 128 + (nb & 3) * 32 + bcol_sel));
                mma_f16(O[0][2 * dp],     pf[0], vfr);
                mma_f16(O[0][2 * dp + 1], pf[0], vfr + 2);
                mma_f16(O[1][2 * dp],     pf[1], vfr);
                mma_f16(O[1][2 * dp + 1], pf[1], vfr + 2);
            }
        }
    }

    __syncthreads();
    float* Ost = (float*)smc;   // [64 d][132] fp32 = 33792 B
#pragma unroll
    for (int mi = 0; mi < 2; mi++) {
        const float inv0 = 1.f / Osum[mi][0];   // row g
        const float inv1 = 1.f / Osum[mi][2];   // row g+8
        const int q0 = wid * 32 + mi * 16 + g;
#pragma unroll
        for (int dt = 0; dt < 8; dt++) {
            int d = dt * 8 + 2 * tig;
            Ost[(d)     * 132 + q0]     = O[mi][dt][0] * inv0;
            Ost[(d + 1) * 132 + q0]     = O[mi][dt][1] * inv0;
            Ost[(d)     * 132 + q0 + 8] = O[mi][dt][2] * inv1;
            Ost[(d + 1) * 132 + q0 + 8] = O[mi][dt][3] * inv1;
        }
    }
    __syncthreads();

    float* og = g_att + (size_t)(b * COUT + head * DK) * L_ + qt;
    for (int i = tid; i < 2048; i += 128) {
        int d = i >> 5, seg = i & 31;
        float4 v = *(const float4*)&Ost[d * 132 + seg * 4];
        *(float4*)&og[(size_t)d * L_ + seg * 4] = v;
    }
}

// ---------------------------------------------------------------------------
// Kernel 3: fc_out + BN + PReLU via fp16 hi/lo HMMA (unchanged).
// ---------------------------------------------------------------------------
#define FC_SMEM 131072
__global__ __launch_bounds__(256, 1)
void fc_hmma(const float* __restrict__ fcw, const float* __restrict__ fcb,
             const float* __restrict__ gamma, const float* __restrict__ beta,
             const float* __restrict__ mean,  const float* __restrict__ var,
             const float* __restrict__ prelu, float* __restrict__ y)
{
    extern __shared__ char smc[];
    const uint32_t smb = smem_u32(smc);
    const int tid = threadIdx.x, wid = tid >> 5, lane = tid & 31;
    const int rt = blockIdx.x * 128;
    const int g = lane >> 2, tig = lane & 3;

    for (int it = tid; it < 4096; it += 256) {
        int r = it >> 5, w4 = (it & 31) * 4;
        float4 v = *(const float4*)&g_att[(size_t)(rt + r) * 128 + w4];
        __half hi[4], lo[4];
        hi[0] = __float2half(v.x); lo[0] = __float2half(v.x - __half2float(hi[0]));
        hi[1] = __float2half(v.y); lo[1] = __float2half(v.y - __half2float(hi[1]));
        hi[2] = __float2half(v.z); lo[2] = __float2half(v.z - __half2float(hi[2]));
        hi[3] = __float2half(v.w); lo[3] = __float2half(v.w - __half2float(hi[3]));
        uint32_t off = SWZ128(r * 128 + (w4 & 63) * 2) + ((w4 >> 6) ? 16384 : 0);
        *(uint2*)(smc + off)         = *(uint2*)hi;
        *(uint2*)(smc + 32768 + off) = *(uint2*)lo;
    }
    for (int it = tid; it < 4096; it += 256) {
        int o = it >> 5, w4 = (it & 31) * 4;
        float4 v = *(const float4*)&fcw[o * 128 + w4];
        __half hi[4], lo[4];
        hi[0] = __float2half(v.x); lo[0] = __float2half(v.x - __half2float(hi[0]));
        hi[1] = __float2half(v.y); lo[1] = __float2half(v.y - __half2float(hi[1]));
        hi[2] = __float2half(v.z); lo[2] = __float2half(v.z - __half2float(hi[2]));
        hi[3] = __float2half(v.w); lo[3] = __float2half(v.w - __half2float(hi[3]));
        uint32_t off = SWZ128(o * 128 + (w4 & 63) * 2) + ((w4 >> 6) ? 16384 : 0);
        *(uint2*)(smc + 65536 + off) = *(uint2*)hi;
        *(uint2*)(smc + 98304 + off) = *(uint2*)lo;
    }
    __syncthreads();

    const uint32_t arow = wid * 16 + (lane & 7) + ((lane >> 3) & 1) * 8;
    const uint32_t acol = (lane >> 4) * 16;
    const uint32_t brow_lo  = (lane & 7) + ((lane >> 4) << 3);
    const uint32_t bcol_sel = ((lane >> 3) & 1) * 16;

    float acc[16][4];
#pragma unroll
    for (int i = 0; i < 16; i++)
#pragma unroll
        for (int j = 0; j < 4; j++) acc[i][j] = 0.f;

#pragma unroll
    for (int kc = 0; kc < 8; kc++) {
        const uint32_t hoff = ((kc >> 2) ? 16384 : 0);
        const int ks = kc & 3;
        uint32_t ah[4], al[4];
        uint32_t aoff = SWZ128(arow * 128 + ks * 32 + acol) + hoff;
        ldsm_x4(ah, smb + aoff);
        ldsm_x4(al, smb + 32768 + aoff);

        uint32_t bh[8][4], bl[8][4];
#pragma unroll
        for (int np = 0; np < 8; np++) {
            uint32_t boff = SWZ128((np * 16 + brow_lo) * 128 + ks * 32 + bcol_sel) + hoff;
            ldsm_x4(bh[np], smb + 65536 + boff);
            ldsm_x4(bl[np], smb + 98304 + boff);
        }
#pragma unroll
        for (int np = 0; np < 8; np++) {
            mma_f16(acc[2 * np],     ah, bh[np]);
            mma_f16(acc[2 * np + 1], ah, bh[np] + 2);
        }
#pragma unroll
        for (int np = 0; np < 8; np++) {
            mma_f16(acc[2 * np],     ah, bl[np]);
            mma_f16(acc[2 * np + 1], ah, bl[np] + 2);
        }
#pragma unroll
        for (int np = 0; np < 8; np++) {
            mma_f16(acc[2 * np],     al, bh[np]);
            mma_f16(acc[2 * np + 1], al, bh[np] + 2);
        }
    }

    const float slope = prelu[0];
    const int r0 = rt + wid * 16 + g;
#pragma unroll
    for (int half = 0; half < 2; half++) {
        const int r = r0 + 8 * half;
        const int c = (r >> 5) & 127;
        const float sc = rsqrtf(var[c] + BN_EPS) * gamma[c];
        const float sh = beta[c] - mean[c] * sc;
#pragma unroll
        for (int nt = 0; nt < 16; nt++) {
            const int o = nt * 8 + tig * 2;
            float v0 = (acc[nt][2 * half]     + fcb[o])     * sc + sh;
            float v1 = (acc[nt][2 * half + 1] + fcb[o + 1]) * sc + sh;
            v0 = (v0 > 0.f) ? v0 : slope * v0;
            v1 = (v1 > 0.f) ? v1 : slope * v1;
            *(float2*)&y[(size_t)r * 128 + o] = make_float2(v0, v1);
        }
    }
}

// ---------------------------------------------------------------------------
extern "C" void kernel_launch(void* const* d_in, const int* in_sizes, int n_in,
                              void* d_out, int out_size)
{
    const float* x     = (const float*)d_in[0];
    const float* wq    = (const float*)d_in[1];
    const float* bq    = (const float*)d_in[2];
    const float* wk    = (const float*)d_in[3];
    const float* bk    = (const float*)d_in[4];
    const float* wv    = (const float*)d_in[5];
    const float* bv    = (const float*)d_in[6];
    const float* fc_w  = (const float*)d_in[7];
    const float* fc_b  = (const float*)d_in[8];
    const float* gam   = (const float*)d_in[9];
    const float* bet   = (const float*)d_in[10];
    const float* mean  = (const float*)d_in[11];
    const float* var   = (const float*)d_in[12];
    const float* prelu = (const float*)d_in[13];
    float* y = (float*)d_out;

    cudaFuncSetAttribute(qkv_hmma, cudaFuncAttributeMaxDynamicSharedMemorySize, QKV_SMEM);
    cudaFuncSetAttribute(attn_mma_kernel, cudaFuncAttributeMaxDynamicSharedMemorySize, SMEM_ATTN);
    cudaFuncSetAttribute(fc_hmma, cudaFuncAttributeMaxDynamicSharedMemorySize, FC_SMEM);

    qkv_hmma<<<dim3(32, B_, 3), 256, QKV_SMEM>>>(x, wq, bq, wk, bk, wv, bv);
    attn_mma_kernel<<<dim3(L_ / 128, NH, B_), 128, SMEM_ATTN>>>();
    fc_hmma<<<128, 256, FC_SMEM>>>(fc_w, fc_b, gam, bet, mean, var, prelu, y);
}

// round 12
// speedup vs baseline: 1.2162x; 1.0487x over previous
#include <cuda_runtime.h>
#include <cuda_fp16.h>
#include <cstdint>

// Problem constants
#define B_    4
#define CIN   128
#define COUT  128
#define H_    32
#define W_    128
#define L_    4096
#define NH    2
#define DK    64
#define BN_EPS 1e-5f

// q is pre-scaled by 0.125 * log2(e) so softmax is exp2(S)
#define QSCALE 0.18033688011112042f

// Device scratch (fp16 operands)
__device__ __half g_qhf[B_ * L_ * COUT];   // [b][l][c]  (pre-scaled)
__device__ __half g_khf[B_ * L_ * COUT];   // [b][l][c]
__device__ __half g_vhf[B_ * COUT * L_];   // [b][c][l]
__device__ float  g_att[B_ * COUT * L_];   // [b][c][l] fp32

#define SWZ128(off) ((off) ^ (((off) >> 3) & 0x70))
#define ONE2 0x3C003C00u   // fp16 {1.0, 1.0}

__device__ __forceinline__ uint32_t smem_u32(const void* p) {
    uint32_t a;
    asm("{ .reg .u64 t; cvta.to.shared.u64 t, %1; cvt.u32.u64 %0, t; }" : "=r"(a) : "l"(p));
    return a;
}
__device__ __forceinline__ void ldsm_x4(uint32_t* r, uint32_t addr) {
    asm volatile("ldmatrix.sync.aligned.m8n8.x4.shared.b16 {%0,%1,%2,%3}, [%4];"
                 : "=r"(r[0]), "=r"(r[1]), "=r"(r[2]), "=r"(r[3]) : "r"(addr));
}
__device__ __forceinline__ void mma_f16(float* d, const uint32_t* a, const uint32_t* b) {
    asm volatile(
        "mma.sync.aligned.m16n8k16.row.col.f32.f16.f16.f32 "
        "{%0,%1,%2,%3}, {%4,%5,%6,%7}, {%8,%9}, {%0,%1,%2,%3};"
        : "+f"(d[0]), "+f"(d[1]), "+f"(d[2]), "+f"(d[3])
        : "r"(a[0]), "r"(a[1]), "r"(a[2]), "r"(a[3]), "r"(b[0]), "r"(b[1]));
}
__device__ __forceinline__ void cp16(uint32_t dst, const void* src) {
    asm volatile("cp.async.ca.shared.global [%0], [%1], 16;" :: "r"(dst), "l"(src));
}
__device__ __forceinline__ uint32_t exp2_f16x2(float lo, float hi) {
    uint32_t s, p;
    asm("cvt.rn.f16x2.f32 %0, %1, %2;" : "=r"(s) : "f"(hi), "f"(lo));
    asm("ex2.approx.f16x2 %0, %1;" : "=r"(p) : "r"(s));
    return p;
}

// ---------------------------------------------------------------------------
// Kernel 1: QKV projection via HMMA, batched-MLP loads, fp16 outputs.
// ---------------------------------------------------------------------------
#define QKV_SMEM 65536
__global__ __launch_bounds__(256, 2)
void qkv_hmma(const float* __restrict__ x,
              const float* __restrict__ wq, const float* __restrict__ bq,
              const float* __restrict__ wk, const float* __restrict__ bk,
              const float* __restrict__ wv, const float* __restrict__ bv)
{
    extern __shared__ char smc[];
    const uint32_t smb = smem_u32(smc);
    const int tid = threadIdx.x, wid = tid >> 5, lane = tid & 31;
    const int lt = blockIdx.x * 128, b = blockIdx.y, which = blockIdx.z;
    const int g = lane >> 2, tig = lane & 3;

    const float* w    = (which == 0) ? wq : (which == 1) ? wk : wv;
    const float* bias = (which == 0) ? bq : (which == 1) ? bk : bv;

    float4 xv[16];
#pragma unroll
    for (int u = 0; u < 16; u++) {
        int it = tid + u * 256;
        int l = it & 127, i4 = (it >> 7) * 4;
        const float* xp = &x[(size_t)(b * CIN + i4) * L_ + lt + l];
        xv[u].x = xp[0];
        xv[u].y = xp[L_];
        xv[u].z = xp[2 * L_];
        xv[u].w = xp[3 * L_];
    }
#pragma unroll
    for (int u = 0; u < 16; u++) {
        int it = tid + u * 256;
        int l = it & 127, i4 = (it >> 7) * 4;
        __half r[4] = {__float2half(xv[u].x), __float2half(xv[u].y),
                       __float2half(xv[u].z), __float2half(xv[u].w)};
        char* base = smc + ((i4 >> 6) ? 16384 : 0);
        *(uint2*)(base + SWZ128(l * 128 + (i4 & 63) * 2)) = *(uint2*)r;
    }
    float4 wv4[16];
#pragma unroll
    for (int u = 0; u < 16; u++) {
        int it = tid + u * 256;
        int o = it >> 5, i4 = (it & 31) * 4;
        wv4[u] = *(const float4*)&w[o * 128 + i4];
    }
#pragma unroll
    for (int u = 0; u < 16; u++) {
        int it = tid + u * 256;
        int o = it >> 5, i4 = (it & 31) * 4;
        __half r[4] = {__float2half(wv4[u].x), __float2half(wv4[u].y),
                       __float2half(wv4[u].z), __float2half(wv4[u].w)};
        char* base = smc + 32768 + ((i4 >> 6) ? 16384 : 0);
        *(uint2*)(base + SWZ128(o * 128 + (i4 & 63) * 2)) = *(uint2*)r;
    }
    __syncthreads();

    const uint32_t arow = wid * 16 + (lane & 7) + ((lane >> 3) & 1) * 8;
    const uint32_t acol = (lane >> 4) * 16;
    const uint32_t brow_lo  = (lane & 7) + ((lane >> 4) << 3);
    const uint32_t bcol_sel = ((lane >> 3) & 1) * 16;
    const int c0 = wid * 16 + g;

    float acc[16][4];
#pragma unroll
    for (int i = 0; i < 16; i++)
#pragma unroll
        for (int j = 0; j < 4; j++) acc[i][j] = 0.f;

#pragma unroll
    for (int kc = 0; kc < 8; kc++) {
        const uint32_t hoff = ((kc >> 2) ? 16384 : 0);
        const int ks = kc & 3;
        uint32_t a4[4];
        ldsm_x4(a4, smb + 32768 + hoff + SWZ128(arow * 128 + ks * 32 + acol));
#pragma unroll
        for (int np = 0; np < 8; np++) {
            uint32_t b4[4];
            ldsm_x4(b4, smb + hoff + SWZ128((np * 16 + brow_lo) * 128 + ks * 32 + bcol_sel));
            mma_f16(acc[2 * np],     a4, b4);
            mma_f16(acc[2 * np + 1], a4, b4 + 2);
        }
    }

    const float b0 = bias[c0], b1 = bias[c0 + 8];
    const float s = (which == 0) ? QSCALE : 1.0f;
    __syncthreads();

    if (which < 2) {
        __half* st = (__half*)smc;
#pragma unroll
        for (int nt = 0; nt < 16; nt++) {
            const int l0 = nt * 8 + tig * 2;
            st[l0 * 128 + c0]           = __float2half((acc[nt][0] + b0) * s);
            st[(l0 + 1) * 128 + c0]     = __float2half((acc[nt][1] + b0) * s);
            st[l0 * 128 + c0 + 8]       = __float2half((acc[nt][2] + b1) * s);
            st[(l0 + 1) * 128 + c0 + 8] = __float2half((acc[nt][3] + b1) * s);
        }
        __syncthreads();
        __half* dst = (which == 0) ? g_qhf : g_khf;
        uint4* dg = (uint4*)&dst[(size_t)(b * L_ + lt) * 128];
        const uint4* sg = (const uint4*)smc;
        for (int i = tid; i < 2048; i += 256) dg[i] = sg[i];
    } else {
        uint32_t* st = (uint32_t*)smc;
#pragma unroll
        for (int nt = 0; nt < 16; nt++) {
            const int lp = (nt * 8 + tig * 2) >> 1;
            __half2 v0 = __floats2half2_rn(acc[nt][0] + b0, acc[nt][1] + b0);
            __half2 v1 = __floats2half2_rn(acc[nt][2] + b1, acc[nt][3] + b1);
            st[c0 * 64 + lp]       = *(uint32_t*)&v0;
            st[(c0 + 8) * 64 + lp] = *(uint32_t*)&v1;
        }
        __syncthreads();
        for (int i = tid; i < 2048; i += 256) {
            int c = i >> 4, seg = i & 15;
            *(uint4*)&g_vhf[(size_t)(b * COUT + c) * L_ + lt + seg * 8] =
                ((const uint4*)smc)[i];
        }
    }
}

// ---------------------------------------------------------------------------
// Kernel 2: FMHA. CTA = (128-q tile, head, batch), 4 warps; warp owns
// 32 q-rows (2 m-tiles) x all 128 keys. 3-STAGE cp.async ring, ONE
// __syncthreads per ktile. Fused per-16-key block: S->exp2->rowsum+PV.
// smem: Q 16K @0; stage s (K 16K + V 16K) @ 16384 + s*32768; total 112K.
// ---------------------------------------------------------------------------
#define OFF_Q   0
#define OFF_S   16384
#define SMEM_ATTN 114688

__device__ __forceinline__ void load_kv_tile(uint32_t smb, int tid, int b, int head,
                                             int kt, int s)
{
    const char* kb = (const char*)g_khf;
    const uint32_t kdst = smb + OFF_S + s * 32768;
    for (int i = tid; i < 1024; i += 128) {
        int r = i >> 3, ch = i & 7;
        const char* src = kb + ((size_t)(b * L_ + kt + r) * COUT + head * DK) * 2 + ch * 16;
        cp16(kdst + SWZ128(r * 128 + ch * 16), src);
    }
    const char* vb = (const char*)g_vhf;
    const uint32_t vdst = kdst + 16384;
    for (int i = tid; i < 1024; i += 128) {
        int half = i >> 9, rem = i & 511;
        int d = rem >> 3, ch = rem & 7;
        const char* src = vb + ((size_t)(b * COUT + head * DK + d) * L_ + kt + half * 64 + ch * 8) * 2;
        cp16(vdst + half * 8192 + SWZ128(d * 128 + ch * 16), src);
    }
}

__global__ __launch_bounds__(128, 2)
void attn_mma_kernel()
{
    extern __shared__ char smc[];
    const uint32_t smb = smem_u32(smc);

    const int tid  = threadIdx.x;
    const int wid  = tid >> 5;
    const int lane = tid & 31;
    const int qt   = blockIdx.x * 128;
    const int head = blockIdx.y;
    const int b    = blockIdx.z;

    const int g   = lane >> 2;
    const int tig = lane & 3;

    // ---- prologue: Q + tiles 0 and 1 (two commit groups) ----
    {
        const char* qb = (const char*)g_qhf;
        for (int i = tid; i < 1024; i += 128) {
            int r = i >> 3, ch = i & 7;
            const char* src = qb + ((size_t)(b * L_ + qt + r) * COUT + head * DK) * 2 + ch * 16;
            cp16(smb + OFF_Q + SWZ128(r * 128 + ch * 16), src);
        }
        load_kv_tile(smb, tid, b, head, 0, 0);
        asm volatile("cp.async.commit_group;" ::: "memory");
        load_kv_tile(smb, tid, b, head, 128, 1);
        asm volatile("cp.async.commit_group;" ::: "memory");
    }

    uint32_t qhr[2][4][4];
    float O[2][8][4];
    float Osum[2][4];
#pragma unroll
    for (int mi = 0; mi < 2; mi++) {
#pragma unroll
        for (int i = 0; i < 8; i++)
#pragma unroll
            for (int j = 0; j < 4; j++) O[mi][i][j] = 0.f;
#pragma unroll
        for (int j = 0; j < 4; j++) Osum[mi][j] = 0.f;
    }
    const uint32_t ones[2] = {ONE2, ONE2};

    const uint32_t brow_lo  = (lane & 7) + ((lane >> 4) << 3);
    const uint32_t bcol_sel = ((lane >> 3) & 1) * 16;

    int buf = 0;   // t % 3
    for (int t = 0; t < 32; t++) {
        if (t < 31) {
            asm volatile("cp.async.wait_group 1;" ::: "memory");
        } else {
            asm volatile("cp.async.wait_group 0;" ::: "memory");
        }
        __syncthreads();   // tile t ready AND all warps done with compute(t-1)

        if (t == 0) {
#pragma unroll
            for (int mi = 0; mi < 2; mi++) {
                const uint32_t arow = wid * 32 + mi * 16 + (lane & 7) + ((lane >> 3) & 1) * 8;
#pragma unroll
                for (int ks = 0; ks < 4; ks++) {
                    uint32_t colb = ks * 32 + (lane >> 4) * 16;
                    ldsm_x4(qhr[mi][ks], smb + OFF_Q + SWZ128(arow * 128 + colb));
                }
            }
        }

        const uint32_t kbase = smb + OFF_S + buf * 32768;
        const uint32_t vbase = kbase + 16384;

        // ---- fused per 16-key block: S -> exp2 -> rowsum + PV ----
#pragma unroll
        for (int nb = 0; nb < 8; nb++) {
            float S8[2][2][4];
#pragma unroll
            for (int mi = 0; mi < 2; mi++)
#pragma unroll
                for (int i = 0; i < 2; i++)
#pragma unroll
                    for (int j = 0; j < 4; j++) S8[mi][i][j] = 0.f;

            const uint32_t krow = nb * 16 + brow_lo;
#pragma unroll
            for (int ks = 0; ks < 4; ks++) {
                uint32_t bh[4];
                ldsm_x4(bh, kbase + SWZ128(krow * 128 + ks * 32 + bcol_sel));
                mma_f16(S8[0][0], qhr[0][ks], bh);
                mma_f16(S8[0][1], qhr[0][ks], bh + 2);
                mma_f16(S8[1][0], qhr[1][ks], bh);
                mma_f16(S8[1][1], qhr[1][ks], bh + 2);
            }

            uint32_t pf[2][4];
#pragma unroll
            for (int mi = 0; mi < 2; mi++) {
                pf[mi][0] = exp2_f16x2(S8[mi][0][0], S8[mi][0][1]);
                pf[mi][1] = exp2_f16x2(S8[mi][0][2], S8[mi][0][3]);
                pf[mi][2] = exp2_f16x2(S8[mi][1][0], S8[mi][1][1]);
                pf[mi][3] = exp2_f16x2(S8[mi][1][2], S8[mi][1][3]);
                mma_f16(Osum[mi], pf[mi], ones);
            }

            const uint32_t vb2 = vbase + ((nb >= 4) ? 8192 : 0);
#pragma unroll
            for (int dp = 0; dp < 4; dp++) {
                uint32_t vfr[4];
                uint32_t row = dp * 16 + brow_lo;
                ldsm_x4(vfr, vb2 + SWZ128(row * 128 + (nb & 3) * 32 + bcol_sel));
                mma_f16(O[0][2 * dp],     pf[0], vfr);
                mma_f16(O[0][2 * dp + 1], pf[0], vfr + 2);
                mma_f16(O[1][2 * dp],     pf[1], vfr);
                mma_f16(O[1][2 * dp + 1], pf[1], vfr + 2);
            }
        }

        // prefetch tile t+2 into buf (t+2)%3 — last used by compute(t-1),
        // which all warps finished before this iteration's barrier.
        if (t + 2 < 32) {
            int nbuf = buf + 2; if (nbuf >= 3) nbuf -= 3;
            load_kv_tile(smb, tid, b, head, (t + 2) * 128, nbuf);
            asm volatile("cp.async.commit_group;" ::: "memory");
        }
        buf = (buf + 1 == 3) ? 0 : buf + 1;
    }

    __syncthreads();
    float* Ost = (float*)smc;   // [64 d][132] fp32 = 33792 B (overlays Q + stage0)
#pragma unroll
    for (int mi = 0; mi < 2; mi++) {
        const float inv0 = 1.f / Osum[mi][0];   // row g
        const float inv1 = 1.f / Osum[mi][2];   // row g+8
        const int q0 = wid * 32 + mi * 16 + g;
#pragma unroll
        for (int dt = 0; dt < 8; dt++) {
            int d = dt * 8 + 2 * tig;
            Ost[(d)     * 132 + q0]     = O[mi][dt][0] * inv0;
            Ost[(d + 1) * 132 + q0]     = O[mi][dt][1] * inv0;
            Ost[(d)     * 132 + q0 + 8] = O[mi][dt][2] * inv1;
            Ost[(d + 1) * 132 + q0 + 8] = O[mi][dt][3] * inv1;
        }
    }
    __syncthreads();

    float* og = g_att + (size_t)(b * COUT + head * DK) * L_ + qt;
    for (int i = tid; i < 2048; i += 128) {
        int d = i >> 5, seg = i & 31;
        float4 v = *(const float4*)&Ost[d * 132 + seg * 4];
        *(float4*)&og[(size_t)d * L_ + seg * 4] = v;
    }
}

// ---------------------------------------------------------------------------
// Kernel 3: fc_out + BN + PReLU via fp16 hi/lo HMMA; batched-MLP prologue.
// ---------------------------------------------------------------------------
#define FC_SMEM 131072
__global__ __launch_bounds__(256, 1)
void fc_hmma(const float* __restrict__ fcw, const float* __restrict__ fcb,
             const float* __restrict__ gamma, const float* __restrict__ beta,
             const float* __restrict__ mean,  const float* __restrict__ var,
             const float* __restrict__ prelu, float* __restrict__ y)
{
    extern __shared__ char smc[];
    const uint32_t smb = smem_u32(smc);
    const int tid = threadIdx.x, wid = tid >> 5, lane = tid & 31;
    const int rt = blockIdx.x * 128;
    const int g = lane >> 2, tig = lane & 3;

    // ---- A: batch 16 LDG.128 (linear addresses), then split+STS ----
    {
        float4 av[16];
#pragma unroll
        for (int u = 0; u < 16; u++) {
            int it = tid + u * 256;
            av[u] = *(const float4*)&g_att[(size_t)rt * 128 + (size_t)it * 4];
        }
#pragma unroll
        for (int u = 0; u < 16; u++) {
            int it = tid + u * 256;
            int r = it >> 5, w4 = (it & 31) * 4;
            __half hi[4], lo[4];
            hi[0] = __float2half(av[u].x); lo[0] = __float2half(av[u].x - __half2float(hi[0]));
            hi[1] = __float2half(av[u].y); lo[1] = __float2half(av[u].y - __half2float(hi[1]));
            hi[2] = __float2half(av[u].z); lo[2] = __float2half(av[u].z - __half2float(hi[2]));
            hi[3] = __float2half(av[u].w); lo[3] = __float2half(av[u].w - __half2float(hi[3]));
            uint32_t off = SWZ128(r * 128 + (w4 & 63) * 2) + ((w4 >> 6) ? 16384 : 0);
            *(uint2*)(smc + off)         = *(uint2*)hi;
            *(uint2*)(smc + 32768 + off) = *(uint2*)lo;
        }
    }
    // ---- F: batch 16 LDG.128, then split+STS ----
    {
        float4 fv[16];
#pragma unroll
        for (int u = 0; u < 16; u++) {
            int it = tid + u * 256;
            fv[u] = *(const float4*)&fcw[(size_t)it * 4];
        }
#pragma unroll
        for (int u = 0; u < 16; u++) {
            int it = tid + u * 256;
            int o = it >> 5, w4 = (it & 31) * 4;
            __half hi[4], lo[4];
            hi[0] = __float2half(fv[u].x); lo[0] = __float2half(fv[u].x - __half2float(hi[0]));
            hi[1] = __float2half(fv[u].y); lo[1] = __float2half(fv[u].y - __half2float(hi[1]));
            hi[2] = __float2half(fv[u].z); lo[2] = __float2half(fv[u].z - __half2float(hi[2]));
            hi[3] = __float2half(fv[u].w); lo[3] = __float2half(fv[u].w - __half2float(hi[3]));
            uint32_t off = SWZ128(o * 128 + (w4 & 63) * 2) + ((w4 >> 6) ? 16384 : 0);
            *(uint2*)(smc + 65536 + off) = *(uint2*)hi;
            *(uint2*)(smc + 98304 + off) = *(uint2*)lo;
        }
    }
    __syncthreads();

    const uint32_t arow = wid * 16 + (lane & 7) + ((lane >> 3) & 1) * 8;
    const uint32_t acol = (lane >> 4) * 16;
    const uint32_t brow_lo  = (lane & 7) + ((lane >> 4) << 3);
    const uint32_t bcol_sel = ((lane >> 3) & 1) * 16;

    float acc[16][4];
#pragma unroll
    for (int i = 0; i < 16; i++)
#pragma unroll
        for (int j = 0; j < 4; j++) acc[i][j] = 0.f;

#pragma unroll
    for (int kc = 0; kc < 8; kc++) {
        const uint32_t hoff = ((kc >> 2) ? 16384 : 0);
        const int ks = kc & 3;
        uint32_t ah[4], al[4];
        uint32_t aoff = SWZ128(arow * 128 + ks * 32 + acol) + hoff;
        ldsm_x4(ah, smb + aoff);
        ldsm_x4(al, smb + 32768 + aoff);

        uint32_t bh[8][4], bl[8][4];
#pragma unroll
        for (int np = 0; np < 8; np++) {
            uint32_t boff = SWZ128((np * 16 + brow_lo) * 128 + ks * 32 + bcol_sel) + hoff;
            ldsm_x4(bh[np], smb + 65536 + boff);
            ldsm_x4(bl[np], smb + 98304 + boff);
        }
#pragma unroll
        for (int np = 0; np < 8; np++) {
            mma_f16(acc[2 * np],     ah, bh[np]);
            mma_f16(acc[2 * np + 1], ah, bh[np] + 2);
        }
#pragma unroll
        for (int np = 0; np < 8; np++) {
            mma_f16(acc[2 * np],     ah, bl[np]);
            mma_f16(acc[2 * np + 1], ah, bl[np] + 2);
        }
#pragma unroll
        for (int np = 0; np < 8; np++) {
            mma_f16(acc[2 * np],     al, bh[np]);
            mma_f16(acc[2 * np + 1], al, bh[np] + 2);
        }
    }

    const float slope = prelu[0];
    const int r0 = rt + wid * 16 + g;
#pragma unroll
    for (int half = 0; half < 2; half++) {
        const int r = r0 + 8 * half;
        const int c = (r >> 5) & 127;
        const float sc = rsqrtf(var[c] + BN_EPS) * gamma[c];
        const float sh = beta[c] - mean[c] * sc;
#pragma unroll
        for (int nt = 0; nt < 16; nt++) {
            const int o = nt * 8 + tig * 2;
            float v0 = (acc[nt][2 * half]     + fcb[o])     * sc + sh;
            float v1 = (acc[nt][2 * half + 1] + fcb[o + 1]) * sc + sh;
            v0 = (v0 > 0.f) ? v0 : slope * v0;
            v1 = (v1 > 0.f) ? v1 : slope * v1;
            *(float2*)&y[(size_t)r * 128 + o] = make_float2(v0, v1);
        }
    }
}

// ---------------------------------------------------------------------------
extern "C" void kernel_launch(void* const* d_in, const int* in_sizes, int n_in,
                              void* d_out, int out_size)
{
    const float* x     = (const float*)d_in[0];
    const float* wq    = (const float*)d_in[1];
    const float* bq    = (const float*)d_in[2];
    const float* wk    = (const float*)d_in[3];
    const float* bk    = (const float*)d_in[4];
    const float* wv    = (const float*)d_in[5];
    const float* bv    = (const float*)d_in[6];
    const float* fc_w  = (const float*)d_in[7];
    const float* fc_b  = (const float*)d_in[8];
    const float* gam   = (const float*)d_in[9];
    const float* bet   = (const float*)d_in[10];
    const float* mean  = (const float*)d_in[11];
    const float* var   = (const float*)d_in[12];
    const float* prelu = (const float*)d_in[13];
    float* y = (float*)d_out;

    cudaFuncSetAttribute(qkv_hmma, cudaFuncAttributeMaxDynamicSharedMemorySize, QKV_SMEM);
    cudaFuncSetAttribute(attn_mma_kernel, cudaFuncAttributeMaxDynamicSharedMemorySize, SMEM_ATTN);
    cudaFuncSetAttribute(fc_hmma, cudaFuncAttributeMaxDynamicSharedMemorySize, FC_SMEM);

    qkv_hmma<<<dim3(32, B_, 3), 256, QKV_SMEM>>>(x, wq, bq, wk, bk, wv, bv);
    attn_mma_kernel<<<dim3(L_ / 128, NH, B_), 128, SMEM_ATTN>>>();
    fc_hmma<<<128, 256, FC_SMEM>>>(fc_w, fc_b, gam, bet, mean, var, prelu, y);
}